// round 6
// baseline (speedup 1.0000x reference)
#include <cuda_runtime.h>

#define V_TOTAL     8192
#define NODE_DIM    256
#define MAX_DEG     64
#define NUM_SAMPLES 16
#define GROUP_DIM   4
#define N_NODES     100000

#define BM 32
#define BN 128
#define BK 32
#define NTHREADS 128
#define NCHUNK (NODE_DIM / BK)   // 8
#define ADST (2 * BM + 2)        // 66 floats per k-row of duplicated A

// Scratch for linear-branch result L = features[ids] @ W + b   (8 MB)
__device__ float g_L[V_TOTAL * NODE_DIM];

// Packed fp32x2 FMA (Blackwell): d = a*b + d, two fp32 lanes per instruction.
#define FMA2(d, a, b) \
    asm("fma.rn.f32x2 %0, %1, %2, %0;" : "+l"(d) : "l"(a), "l"(b))

static __device__ __forceinline__ float2 unpack_f32x2(unsigned long long v) {
    float2 r;
    asm("mov.b64 {%0, %1}, %2;" : "=f"(r.x), "=f"(r.y) : "l"(v));
    return r;
}

#define CP_ASYNC16(smem_u32, gptr) \
    asm volatile("cp.async.cg.shared.global [%0], [%1], 16;" \
                 :: "r"(smem_u32), "l"(gptr))
#define CP_COMMIT()  asm volatile("cp.async.commit_group;")
#define CP_WAIT0()   asm volatile("cp.async.wait_group 0;")

// ---------------------------------------------------------------------------
// Kernel 1: L = features[ids] @ W + b   (M=8192, N=256, K=256, fp32)
// 32x128 block tile, 128 threads, 4x8 microtile, grid (256,2)=512 blocks
// (fine-grained -> good wave balance at ~4 blocks/SM).
// A stored PRE-DUPLICATED in smem ({a,a} pairs): inner loop reads one
// broadcast LDS.64 per m-row -> packed f32x2 operand with zero MOVs.
// B tile [k][n]: LDS.128 at tx*4 / 64+tx*4 (conflict-free, proven R4).
// B filled via cp.async (no prefetch registers); A via register prefetch.
// Double-buffered, one __syncthreads per BK chunk.
// ---------------------------------------------------------------------------
__global__ void __launch_bounds__(NTHREADS) linear_kernel(
    const int*   __restrict__ ids,
    const float* __restrict__ features,
    const float* __restrict__ W,
    const float* __restrict__ b)
{
    __shared__ float As[2][BK][ADST];   // duplicated A, 16.9 KB
    __shared__ float Bs[2][BK][BN];     // 32 KB
    __shared__ int   rowid[BM];

    const int tid = threadIdx.x;
    const int tx  = tid & 15;           // n-dir: cols tx*4..+3 and 64+tx*4..+3
    const int ty  = tid >> 4;           // m-dir: 8 thread-rows * 4 m-rows
    const int m0  = blockIdx.x * BM;
    const int n0  = blockIdx.y * BN;

    if (tid < BM) rowid[tid] = ids[m0 + tid];
    __syncthreads();

    // A fill: 32 rows x 32 floats = 256 float4; 2 per thread (rows ar, ar+16).
    const int ar = tid >> 3;            // 0..15
    const int ac = (tid & 7) * 4;       // k-offset within chunk
    // B fill: 32 x 128 = 1024 float4; 8 per thread via cp.async.
    const int bkr = tid >> 5;           // 0..3 -> k-rows bkr + 4j
    const int bc  = (tid & 31) * 4;

    const size_t rowA0 = (size_t)rowid[ar]      * NODE_DIM;
    const size_t rowA1 = (size_t)rowid[ar + 16] * NODE_DIM;
    const float* Wb = W + n0 + bc;

    unsigned long long acc[4][4];
#pragma unroll
    for (int i = 0; i < 4; i++)
#pragma unroll
        for (int j = 0; j < 4; j++) acc[i][j] = 0ull;

    // ---- Prologue: fill chunk 0 ----
    {
        const float4 a0 = *(const float4*)&features[rowA0 + ac];
        const float4 a1 = *(const float4*)&features[rowA1 + ac];
        As[0][ac + 0][2 * ar] = a0.x;  As[0][ac + 0][2 * ar + 1] = a0.x;
        As[0][ac + 1][2 * ar] = a0.y;  As[0][ac + 1][2 * ar + 1] = a0.y;
        As[0][ac + 2][2 * ar] = a0.z;  As[0][ac + 2][2 * ar + 1] = a0.z;
        As[0][ac + 3][2 * ar] = a0.w;  As[0][ac + 3][2 * ar + 1] = a0.w;
        const int ar2 = 2 * (ar + 16);
        As[0][ac + 0][ar2] = a1.x;  As[0][ac + 0][ar2 + 1] = a1.x;
        As[0][ac + 1][ar2] = a1.y;  As[0][ac + 1][ar2 + 1] = a1.y;
        As[0][ac + 2][ar2] = a1.z;  As[0][ac + 2][ar2 + 1] = a1.z;
        As[0][ac + 3][ar2] = a1.w;  As[0][ac + 3][ar2 + 1] = a1.w;
#pragma unroll
        for (int j = 0; j < 8; j++) {
            const unsigned sm = (unsigned)__cvta_generic_to_shared(
                &Bs[0][bkr + 4 * j][bc]);
            CP_ASYNC16(sm, &Wb[(size_t)(bkr + 4 * j) * NODE_DIM]);
        }
        CP_COMMIT();
        CP_WAIT0();
    }
    __syncthreads();

    int buf = 0;
#pragma unroll
    for (int c = 0; c < NCHUNK; c++) {
        float4 pa0, pa1;
        if (c + 1 < NCHUNK) {
            const int kc = (c + 1) * BK;
            pa0 = *(const float4*)&features[rowA0 + kc + ac];
            pa1 = *(const float4*)&features[rowA1 + kc + ac];
#pragma unroll
            for (int j = 0; j < 8; j++) {
                const unsigned sm = (unsigned)__cvta_generic_to_shared(
                    &Bs[buf ^ 1][bkr + 4 * j][bc]);
                CP_ASYNC16(sm, &Wb[(size_t)(kc + bkr + 4 * j) * NODE_DIM]);
            }
            CP_COMMIT();
        }

#pragma unroll
        for (int k = 0; k < BK; k++) {
            const unsigned long long a0 =
                *(const unsigned long long*)&As[buf][k][2 * (ty * 4 + 0)];
            const unsigned long long a1 =
                *(const unsigned long long*)&As[buf][k][2 * (ty * 4 + 1)];
            const unsigned long long a2 =
                *(const unsigned long long*)&As[buf][k][2 * (ty * 4 + 2)];
            const unsigned long long a3 =
                *(const unsigned long long*)&As[buf][k][2 * (ty * 4 + 3)];
            const ulonglong2 b01 = *(const ulonglong2*)&Bs[buf][k][tx * 4];
            const ulonglong2 b23 = *(const ulonglong2*)&Bs[buf][k][64 + tx * 4];

            FMA2(acc[0][0], a0, b01.x); FMA2(acc[0][1], a0, b01.y);
            FMA2(acc[0][2], a0, b23.x); FMA2(acc[0][3], a0, b23.y);
            FMA2(acc[1][0], a1, b01.x); FMA2(acc[1][1], a1, b01.y);
            FMA2(acc[1][2], a1, b23.x); FMA2(acc[1][3], a1, b23.y);
            FMA2(acc[2][0], a2, b01.x); FMA2(acc[2][1], a2, b01.y);
            FMA2(acc[2][2], a2, b23.x); FMA2(acc[2][3], a2, b23.y);
            FMA2(acc[3][0], a3, b01.x); FMA2(acc[3][1], a3, b01.y);
            FMA2(acc[3][2], a3, b23.x); FMA2(acc[3][3], a3, b23.y);
        }

        if (c + 1 < NCHUNK) {
            const int nb = buf ^ 1;
            As[nb][ac + 0][2 * ar] = pa0.x;  As[nb][ac + 0][2 * ar + 1] = pa0.x;
            As[nb][ac + 1][2 * ar] = pa0.y;  As[nb][ac + 1][2 * ar + 1] = pa0.y;
            As[nb][ac + 2][2 * ar] = pa0.z;  As[nb][ac + 2][2 * ar + 1] = pa0.z;
            As[nb][ac + 3][2 * ar] = pa0.w;  As[nb][ac + 3][2 * ar + 1] = pa0.w;
            const int ar2 = 2 * (ar + 16);
            As[nb][ac + 0][ar2] = pa1.x;  As[nb][ac + 0][ar2 + 1] = pa1.x;
            As[nb][ac + 1][ar2] = pa1.y;  As[nb][ac + 1][ar2 + 1] = pa1.y;
            As[nb][ac + 2][ar2] = pa1.z;  As[nb][ac + 2][ar2 + 1] = pa1.z;
            As[nb][ac + 3][ar2] = pa1.w;  As[nb][ac + 3][ar2 + 1] = pa1.w;
            CP_WAIT0();
        }
        __syncthreads();
        buf ^= 1;
    }

    const float4 bias0 = *(const float4*)&b[n0 + tx * 4];
    const float4 bias1 = *(const float4*)&b[n0 + 64 + tx * 4];
#pragma unroll
    for (int i = 0; i < 4; i++) {
        const float2 p0 = unpack_f32x2(acc[i][0]);
        const float2 p1 = unpack_f32x2(acc[i][1]);
        const float2 p2 = unpack_f32x2(acc[i][2]);
        const float2 p3 = unpack_f32x2(acc[i][3]);
        float4 o0, o1;
        o0.x = p0.x + bias0.x;  o0.y = p0.y + bias0.y;
        o0.z = p1.x + bias0.z;  o0.w = p1.y + bias0.w;
        o1.x = p2.x + bias1.x;  o1.y = p2.y + bias1.y;
        o1.z = p3.x + bias1.z;  o1.w = p3.y + bias1.w;
        const int m = m0 + ty * 4 + i;
        *(float4*)&g_L[(size_t)m * NODE_DIM + n0 + tx * 4]      = o0;
        *(float4*)&g_L[(size_t)m * NODE_DIM + n0 + 64 + tx * 4] = o1;
    }
}

// ---------------------------------------------------------------------------
// Kernel 2: per-v neighbor scoring + grouped argmin + outputs (R1 version:
// 32 regs, ~94% occ — at the aggregate L2 gather wall, ~45 us floor).
//
// Output layout (float32):
//   [0,            131072)  sel  (node ids, exact in fp32)
//   [131072,       262144)  att  (all 1.0)
//   [262144,       270336)  numnz
//   [270336,       278528)  numnz (duplicate)
// ---------------------------------------------------------------------------
__global__ void __launch_bounds__(256) sampler_kernel(
    const int*   __restrict__ ids,
    const int*   __restrict__ adj,
    const float* __restrict__ features,
    float*       __restrict__ out)
{
    __shared__ float ls[NODE_DIM];
    __shared__ float scores[MAX_DEG];
    __shared__ int   nbr[MAX_DEG];
    __shared__ float flags[NUM_SAMPLES];

    const int v    = blockIdx.x;
    const int tid  = threadIdx.x;
    const int lane = tid & 31;
    const int w    = tid >> 5;

    const int vid = __ldg(&ids[v]);

    ls[tid] = g_L[(size_t)v * NODE_DIM + tid];
    if (tid < MAX_DEG) nbr[tid] = adj[(size_t)vid * MAX_DEG + tid];
    __syncthreads();

    const float4 lv0 = ((const float4*)ls)[lane];
    const float4 lv1 = ((const float4*)ls)[lane + 32];

#pragma unroll
    for (int t = 0; t < 8; t++) {
        const int k  = w * 8 + t;
        const int nb = nbr[k];
        const float4* fr = (const float4*)(features + (size_t)nb * NODE_DIM);
        const float4 f0 = __ldg(&fr[lane]);
        const float4 f1 = __ldg(&fr[lane + 32]);

        float s = f0.x * lv0.x + f0.y * lv0.y + f0.z * lv0.z + f0.w * lv0.w
                + f1.x * lv1.x + f1.y * lv1.y + f1.z * lv1.z + f1.w * lv1.w;

#pragma unroll
        for (int off = 16; off > 0; off >>= 1)
            s += __shfl_xor_sync(0xffffffffu, s, off);

        if (lane == 0) scores[k] = fmaxf(s, 0.0f);
    }
    __syncthreads();

    if (tid < NUM_SAMPLES) {
        const int base = tid * GROUP_DIM;
        float m  = scores[base];
        int   bi = 0;
#pragma unroll
        for (int g = 1; g < GROUP_DIM; g++) {
            float sc = scores[base + g];
            if (sc < m) { m = sc; bi = g; }       // strict <  => first min
        }
        const int sid = nbr[base + bi];
        out[(size_t)v * NUM_SAMPLES + tid]                          = (float)sid;
        out[(size_t)V_TOTAL * NUM_SAMPLES + v * NUM_SAMPLES + tid]  = 1.0f;
        flags[tid] = (sid == N_NODES - 1) ? 0.0f : 1.0f;
    }
    __syncthreads();

    if (tid == 0) {
        float nn = 0.0f;
#pragma unroll
        for (int s = 0; s < NUM_SAMPLES; s++) nn += flags[s];
        out[2 * V_TOTAL * NUM_SAMPLES + v]           = nn;
        out[2 * V_TOTAL * NUM_SAMPLES + V_TOTAL + v] = nn;
    }
}

extern "C" void kernel_launch(void* const* d_in, const int* in_sizes, int n_in,
                              void* d_out, int out_size)
{
    const int*   ids      = (const int*)  d_in[0];
    const int*   adj      = (const int*)  d_in[1];
    const float* features = (const float*)d_in[2];
    const float* W        = (const float*)d_in[3];
    const float* b        = (const float*)d_in[4];
    float*       out      = (float*)d_out;

    linear_kernel<<<dim3(V_TOTAL / BM, NODE_DIM / BN), NTHREADS>>>(ids, features, W, b);
    sampler_kernel<<<V_TOTAL, 256>>>(ids, adj, features, out);
}